// round 3
// baseline (speedup 1.0000x reference)
#include <cuda_runtime.h>
#include <math.h>

// ---------------- problem constants ----------------
#define L_   12
#define B_   4
#define S_   512
#define D_   768
#define H_   12
#define DH_  64
#define FF_  3072
#define BH_  (B_*H_)        // 48
#define MR_  (B_*S_)        // 2048 rows of hidden
#define SS_  (S_*S_)        // 262144

// ---------------- scratch (device globals; allocation-free) ----------------
__device__ float g_bias  [BH_*SS_];     // (rel+rel2)*scale + mask, layer-invariant
__device__ float g_scores[BH_*SS_];
__device__ float g_q  [BH_*S_*DH_];
__device__ float g_k  [BH_*S_*DH_];
__device__ float g_v  [BH_*S_*DH_];
__device__ float g_ctx [MR_*D_];
__device__ float g_h   [MR_*D_];
__device__ float g_tmp [MR_*D_];
__device__ float g_attn[MR_*D_];
__device__ float g_ff  [MR_*FF_];

// ---------------- small kernels ----------------
__global__ void bias_kernel(const float* __restrict__ rel,
                            const float* __restrict__ rel2,
                            const float* __restrict__ mask)
{
    long i = (long)blockIdx.x * 256 + threadIdx.x;
    if (i >= (long)BH_ * SS_) return;
    int b = (int)(i / ((long)H_ * SS_));
    int kcol = (int)(i & (S_ - 1));
    g_bias[i] = (rel[i] + rel2[i]) * 0.125f + mask[b * S_ + kcol];
}

__global__ void copy_kernel(const float* __restrict__ src, float* __restrict__ dst, long n)
{
    long i = (long)blockIdx.x * 256 + threadIdx.x;
    if (i < n) dst[i] = src[i];
}

// ---------------- generic NN SGEMM: C = A[M,K] @ W[K,N] (+ epilogue) ----------------
// BM=BN=64, BK=16, 256 threads, 4x4 per thread. All dims assumed divisible.
// EPI: 1 = qkv scatter to [B,H,S,DH] with (acc+bias)*scale
//      2 = acc + bias[n] + res[m*N+n]
//      3 = gelu(acc + bias[n])        (exact erf)
//      4 = ctx gather: z=(b*H+h), write C[(b*S+m)*D + h*DH + n]
template<int EPI>
__global__ __launch_bounds__(256)
void gemm_nn(const float* __restrict__ A, const float* __restrict__ W,
             float* __restrict__ C,
             const float* __restrict__ bias, const float* __restrict__ res,
             int M, int N, int K, long sA, long sW, float scaleval)
{
    int z = blockIdx.z;
    A += (long)z * sA;
    W += (long)z * sW;

    __shared__ float As[16][64];
    __shared__ float Bs[16][64];

    int tid = threadIdx.x;
    int tx = tid & 15, ty = tid >> 4;
    float acc[4][4] = {};

    int lr = tid >> 2;            // A-load row in tile (0..63)
    int lc = (tid & 3) << 2;      // A-load k offset (0,4,8,12)
    int br = tid >> 4;            // W-load k row (0..15)
    int bc = (tid & 15) << 2;     // W-load col offset

    const float* Abase = A + (long)(blockIdx.y * 64 + lr) * K + lc;
    const float* Wbase = W + (long)br * N + blockIdx.x * 64 + bc;

    for (int k0 = 0; k0 < K; k0 += 16) {
        float4 av = *(const float4*)(Abase + k0);
        As[lc + 0][lr] = av.x; As[lc + 1][lr] = av.y;
        As[lc + 2][lr] = av.z; As[lc + 3][lr] = av.w;
        float4 wv = *(const float4*)(Wbase + (long)k0 * N);
        *(float4*)&Bs[br][bc] = wv;
        __syncthreads();
#pragma unroll
        for (int kk = 0; kk < 16; kk++) {
            float a0 = As[kk][ty * 4 + 0], a1 = As[kk][ty * 4 + 1];
            float a2 = As[kk][ty * 4 + 2], a3 = As[kk][ty * 4 + 3];
            float b0 = Bs[kk][tx * 4 + 0], b1 = Bs[kk][tx * 4 + 1];
            float b2 = Bs[kk][tx * 4 + 2], b3 = Bs[kk][tx * 4 + 3];
            acc[0][0] += a0 * b0; acc[0][1] += a0 * b1; acc[0][2] += a0 * b2; acc[0][3] += a0 * b3;
            acc[1][0] += a1 * b0; acc[1][1] += a1 * b1; acc[1][2] += a1 * b2; acc[1][3] += a1 * b3;
            acc[2][0] += a2 * b0; acc[2][1] += a2 * b1; acc[2][2] += a2 * b2; acc[2][3] += a2 * b3;
            acc[3][0] += a3 * b0; acc[3][1] += a3 * b1; acc[3][2] += a3 * b2; acc[3][3] += a3 * b3;
        }
        __syncthreads();
    }

    int m0 = blockIdx.y * 64 + ty * 4;
    int n0 = blockIdx.x * 64 + tx * 4;
#pragma unroll
    for (int i = 0; i < 4; i++) {
        int m = m0 + i;
#pragma unroll
        for (int j = 0; j < 4; j++) {
            int n = n0 + j;
            float v = acc[i][j];
            if (EPI == 1) {
                v = (v + bias[n]) * scaleval;
                int b = m >> 9, s = m & 511, hh = n >> 6, d = n & 63;
                g_q[0]; // no-op to keep template happy under -O3 (optimized out)
                C[((((long)b * H_ + hh) * S_ + s) * DH_) + d] = v;
            } else if (EPI == 2) {
                C[(long)m * N + n] = v + bias[n] + res[(long)m * N + n];
            } else if (EPI == 3) {
                float x = v + bias[n];
                C[(long)m * N + n] = 0.5f * x * (1.0f + erff(x * 0.70710678118654752f));
            } else if (EPI == 4) {
                int b = z / H_, hh = z % H_;
                C[((long)(b * S_ + m)) * D_ + hh * DH_ + n] = v;
            }
        }
    }
}

// ---------------- batched NT SGEMM for scores: C = Q @ K^T + biasmat ----------------
__global__ __launch_bounds__(256)
void gemm_nt_scores(const float* __restrict__ Q, const float* __restrict__ Kmat,
                    const float* __restrict__ biasmat, float* __restrict__ C)
{
    int z = blockIdx.z;
    const float* A  = Q    + (long)z * S_ * DH_;
    const float* Bm = Kmat + (long)z * S_ * DH_;
    float*       Cz = C    + (long)z * SS_;
    const float* bz = biasmat + (long)z * SS_;

    __shared__ float As[16][64];
    __shared__ float Bs[16][64];
    int tid = threadIdx.x;
    int tx = tid & 15, ty = tid >> 4;
    float acc[4][4] = {};

    int lr = tid >> 2, lc = (tid & 3) << 2;
    const float* Abase = A  + (long)(blockIdx.y * 64 + lr) * DH_ + lc;
    const float* Bbase = Bm + (long)(blockIdx.x * 64 + lr) * DH_ + lc;

    for (int k0 = 0; k0 < DH_; k0 += 16) {
        float4 av = *(const float4*)(Abase + k0);
        As[lc + 0][lr] = av.x; As[lc + 1][lr] = av.y;
        As[lc + 2][lr] = av.z; As[lc + 3][lr] = av.w;
        float4 bv = *(const float4*)(Bbase + k0);
        Bs[lc + 0][lr] = bv.x; Bs[lc + 1][lr] = bv.y;
        Bs[lc + 2][lr] = bv.z; Bs[lc + 3][lr] = bv.w;
        __syncthreads();
#pragma unroll
        for (int kk = 0; kk < 16; kk++) {
            float a0 = As[kk][ty * 4 + 0], a1 = As[kk][ty * 4 + 1];
            float a2 = As[kk][ty * 4 + 2], a3 = As[kk][ty * 4 + 3];
            float b0 = Bs[kk][tx * 4 + 0], b1 = Bs[kk][tx * 4 + 1];
            float b2 = Bs[kk][tx * 4 + 2], b3 = Bs[kk][tx * 4 + 3];
            acc[0][0] += a0 * b0; acc[0][1] += a0 * b1; acc[0][2] += a0 * b2; acc[0][3] += a0 * b3;
            acc[1][0] += a1 * b0; acc[1][1] += a1 * b1; acc[1][2] += a1 * b2; acc[1][3] += a1 * b3;
            acc[2][0] += a2 * b0; acc[2][1] += a2 * b1; acc[2][2] += a2 * b2; acc[2][3] += a2 * b3;
            acc[3][0] += a3 * b0; acc[3][1] += a3 * b1; acc[3][2] += a3 * b2; acc[3][3] += a3 * b3;
        }
        __syncthreads();
    }

    int m0 = blockIdx.y * 64 + ty * 4;
    int n0 = blockIdx.x * 64 + tx * 4;
#pragma unroll
    for (int i = 0; i < 4; i++)
#pragma unroll
        for (int j = 0; j < 4; j++) {
            long idx = (long)(m0 + i) * S_ + (n0 + j);
            Cz[idx] = acc[i][j] + bz[idx];
        }
}

// ---------------- softmax over rows of length 512 ----------------
__global__ __launch_bounds__(256)
void softmax512(float* __restrict__ sc)
{
    float* row = sc + (long)blockIdx.x * S_;
    int tid = threadIdx.x;
    float v0 = row[tid], v1 = row[tid + 256];
    __shared__ float red[8];

    float m = fmaxf(v0, v1);
#pragma unroll
    for (int o = 16; o; o >>= 1) m = fmaxf(m, __shfl_xor_sync(0xffffffffu, m, o));
    if ((tid & 31) == 0) red[tid >> 5] = m;
    __syncthreads();
    m = fmaxf(fmaxf(fmaxf(red[0], red[1]), fmaxf(red[2], red[3])),
              fmaxf(fmaxf(red[4], red[5]), fmaxf(red[6], red[7])));
    __syncthreads();

    float e0 = __expf(v0 - m), e1 = __expf(v1 - m);
    float s = e0 + e1;
#pragma unroll
    for (int o = 16; o; o >>= 1) s += __shfl_xor_sync(0xffffffffu, s, o);
    if ((tid & 31) == 0) red[tid >> 5] = s;
    __syncthreads();
    s = (red[0] + red[1]) + (red[2] + red[3]) + (red[4] + red[5]) + (red[6] + red[7]);
    float inv = 1.0f / s;
    row[tid]       = e0 * inv;
    row[tid + 256] = e1 * inv;
}

// ---------------- layernorm over rows of length 768 ----------------
__global__ __launch_bounds__(256)
void layernorm768(const float* __restrict__ x, const float* __restrict__ g,
                  const float* __restrict__ b, float* __restrict__ y)
{
    const float* row = x + (long)blockIdx.x * D_;
    float* orow = y + (long)blockIdx.x * D_;
    int tid = threadIdx.x;
    float a0 = row[tid], a1 = row[tid + 256], a2 = row[tid + 512];
    float s = a0 + a1 + a2;
    float q = a0 * a0 + a1 * a1 + a2 * a2;
    __shared__ float rs[8], rq[8];
#pragma unroll
    for (int o = 16; o; o >>= 1) {
        s += __shfl_xor_sync(0xffffffffu, s, o);
        q += __shfl_xor_sync(0xffffffffu, q, o);
    }
    if ((tid & 31) == 0) { rs[tid >> 5] = s; rq[tid >> 5] = q; }
    __syncthreads();
    s = (rs[0] + rs[1]) + (rs[2] + rs[3]) + (rs[4] + rs[5]) + (rs[6] + rs[7]);
    q = (rq[0] + rq[1]) + (rq[2] + rq[3]) + (rq[4] + rq[5]) + (rq[6] + rq[7]);
    float mean = s * (1.0f / D_);
    float var  = q * (1.0f / D_) - mean * mean;
    float r = rsqrtf(var + 1e-5f);
    orow[tid]       = (a0 - mean) * r * g[tid]       + b[tid];
    orow[tid + 256] = (a1 - mean) * r * g[tid + 256] + b[tid + 256];
    orow[tid + 512] = (a2 - mean) * r * g[tid + 512] + b[tid + 512];
}

// ---------------- host orchestration ----------------
extern "C" void kernel_launch(void* const* d_in, const int* in_sizes, int n_in,
                              void* d_out, int out_size)
{
    const float* hs    = (const float*)d_in[0];
    const float* mask  = (const float*)d_in[1];
    const float* rel   = (const float*)d_in[2];
    const float* rel2  = (const float*)d_in[3];
    const float* Wq    = (const float*)d_in[4];
    const float* bq    = (const float*)d_in[5];
    const float* Wk    = (const float*)d_in[6];
    const float* bk    = (const float*)d_in[7];
    const float* Wv    = (const float*)d_in[8];
    const float* bv    = (const float*)d_in[9];
    const float* Wo    = (const float*)d_in[10];
    const float* bo    = (const float*)d_in[11];
    const float* ln1g  = (const float*)d_in[12];
    const float* ln1b  = (const float*)d_in[13];
    const float* Wi    = (const float*)d_in[14];
    const float* bi    = (const float*)d_in[15];
    const float* Wo2   = (const float*)d_in[16];
    const float* bo2   = (const float*)d_in[17];
    const float* ln2g  = (const float*)d_in[18];
    const float* ln2b  = (const float*)d_in[19];
    float* out = (float*)d_out;

    float *p_bias, *p_scores, *p_q, *p_k, *p_v, *p_ctx, *p_h, *p_tmp, *p_attn, *p_ff;
    cudaGetSymbolAddress((void**)&p_bias,   g_bias);
    cudaGetSymbolAddress((void**)&p_scores, g_scores);
    cudaGetSymbolAddress((void**)&p_q,      g_q);
    cudaGetSymbolAddress((void**)&p_k,      g_k);
    cudaGetSymbolAddress((void**)&p_v,      g_v);
    cudaGetSymbolAddress((void**)&p_ctx,    g_ctx);
    cudaGetSymbolAddress((void**)&p_h,      g_h);
    cudaGetSymbolAddress((void**)&p_tmp,    g_tmp);
    cudaGetSymbolAddress((void**)&p_attn,   g_attn);
    cudaGetSymbolAddress((void**)&p_ff,     g_ff);

    long nb = (long)BH_ * SS_;
    bias_kernel<<<(unsigned)((nb + 255) / 256), 256>>>(rel, rel2, mask);
    copy_kernel<<<(MR_ * D_ + 255) / 256, 256>>>(hs, p_h, (long)MR_ * D_);

    dim3 gQKV(D_ / 64, MR_ / 64, 1);        // 12 x 32
    dim3 gS  (S_ / 64, S_ / 64, BH_);       // 8 x 8 x 48
    dim3 gC  (DH_ / 64, S_ / 64, BH_);      // 1 x 8 x 48
    dim3 gF1 (FF_ / 64, MR_ / 64, 1);       // 48 x 32

    for (int l = 0; l < L_; l++) {
        const float* wq  = Wq  + (long)l * D_ * D_;
        const float* wk  = Wk  + (long)l * D_ * D_;
        const float* wv  = Wv  + (long)l * D_ * D_;
        const float* wo  = Wo  + (long)l * D_ * D_;
        const float* wi  = Wi  + (long)l * D_ * FF_;
        const float* wo2 = Wo2 + (long)l * FF_ * D_;

        // QKV projections (q folds 1/sqrt(DH)), scattered to [B,H,S,DH]
        gemm_nn<1><<<gQKV, 256>>>(p_h, wq, p_q, bq + l * D_, nullptr,
                                  MR_, D_, D_, 0, 0, 0.125f);
        gemm_nn<1><<<gQKV, 256>>>(p_h, wk, p_k, bk + l * D_, nullptr,
                                  MR_, D_, D_, 0, 0, 1.0f);
        gemm_nn<1><<<gQKV, 256>>>(p_h, wv, p_v, bv + l * D_, nullptr,
                                  MR_, D_, D_, 0, 0, 1.0f);

        // scores = q @ k^T + bias ; softmax (PB-Relax == standard safe softmax)
        gemm_nt_scores<<<gS, 256>>>(p_q, p_k, p_bias, p_scores);
        softmax512<<<BH_ * S_, 256>>>(p_scores);

        // ctx = probs @ v, gathered back to [B,S,D]
        gemm_nn<4><<<gC, 256>>>(p_scores, p_v, p_ctx, nullptr, nullptr,
                                S_, DH_, S_, (long)SS_, (long)S_ * DH_, 1.0f);

        // attn_out = LN1(ctx @ Wo + bo + h)
        gemm_nn<2><<<gQKV, 256>>>(p_ctx, wo, p_tmp, bo + l * D_, p_h,
                                  MR_, D_, D_, 0, 0, 1.0f);
        layernorm768<<<MR_, 256>>>(p_tmp, ln1g + l * D_, ln1b + l * D_, p_attn);

        // ff = gelu(attn @ Wi + bi)
        gemm_nn<3><<<gF1, 256>>>(p_attn, wi, p_ff, bi + l * FF_, nullptr,
                                 MR_, FF_, D_, 0, 0, 1.0f);

        // out = LN2(ff @ Wo2 + bo2 + attn_out)
        gemm_nn<2><<<gQKV, 256>>>(p_ff, wo2, p_tmp, bo2 + l * D_, p_attn,
                                  MR_, D_, FF_, 0, 0, 1.0f);
        float* dst = (l == L_ - 1) ? out : p_h;
        layernorm768<<<MR_, 256>>>(p_tmp, ln2g + l * D_, ln2b + l * D_, dst);
    }
}

// round 4
// speedup vs baseline: 1.3509x; 1.3509x over previous
#include <cuda_runtime.h>
#include <math.h>
#include <stdint.h>

// ---------------- problem constants ----------------
#define L_   12
#define B_   4
#define S_   512
#define D_   768
#define H_   12
#define DH_  64
#define FF_  3072
#define BH_  (B_*H_)        // 48
#define MR_  (B_*S_)        // 2048 rows of hidden
#define SS_  (S_*S_)        // 262144

// ---------------- scratch (device globals; allocation-free) ----------------
__device__ float g_bias  [BH_*SS_];     // (rel+rel2)*scale + mask, layer-invariant
__device__ float g_scores[BH_*SS_];
__device__ float g_q  [BH_*S_*DH_];
__device__ float g_k  [BH_*S_*DH_];
__device__ float g_v  [BH_*S_*DH_];
__device__ float g_ctx [MR_*D_];
__device__ float g_h   [MR_*D_];
__device__ float g_tmp [MR_*D_];
__device__ float g_attn[MR_*D_];
__device__ float g_ff  [MR_*FF_];

// ---------------- helpers ----------------
__device__ __forceinline__ float to_tf32(float x)
{
    float r;
    asm("cvt.rna.tf32.f32 %0, %1;" : "=f"(r) : "f"(x));
    return r;
}

__device__ __forceinline__ void mma_tf32(float* c, const uint32_t* a, const uint32_t* b)
{
    asm("mma.sync.aligned.m16n8k8.row.col.f32.tf32.tf32.f32 "
        "{%0,%1,%2,%3}, {%4,%5,%6,%7}, {%8,%9}, {%0,%1,%2,%3};"
        : "+f"(c[0]), "+f"(c[1]), "+f"(c[2]), "+f"(c[3])
        : "r"(a[0]), "r"(a[1]), "r"(a[2]), "r"(a[3]),
          "r"(b[0]), "r"(b[1]));
}

// ---------------- small kernels ----------------
__global__ void bias_kernel(const float* __restrict__ rel,
                            const float* __restrict__ rel2,
                            const float* __restrict__ mask)
{
    long i = (long)blockIdx.x * 256 + threadIdx.x;
    if (i >= (long)BH_ * SS_) return;
    int b = (int)(i / ((long)H_ * SS_));
    int kcol = (int)(i & (S_ - 1));
    g_bias[i] = (rel[i] + rel2[i]) * 0.125f + mask[b * S_ + kcol];
}

__global__ void copy_kernel(const float* __restrict__ src, float* __restrict__ dst, long n)
{
    long i = (long)blockIdx.x * 256 + threadIdx.x;
    if (i < n) dst[i] = src[i];
}

// ---------------- tensor-core TF32 GEMM ----------------
// C = A[M,K] @ B (NN: B[K,N]; NT: B[N,K], i.e. C = A @ B^T) with epilogue.
// BM=128, BK=16, 256 threads (8 warps). Warp tile = (BM/WARPS_M) x (BN/WARPS_N).
// mma.sync m16n8k8 tf32. All dims divisible by tile sizes.
// EPI: 1 = qkv scatter to [B,H,S,DH], v=(acc+bias[n])*scale
//      2 = acc + bias[n] + res[m*N+n]
//      3 = gelu(acc + bias[n])   (exact erf)
//      4 = ctx gather: C[(b*S+m)*D + h*DH + n], z=b*H+h
//      5 = scores: C[m*S+n] = acc + res[m*S+n]   (C,res z-strided)
template<int BN, int WARPS_M, int WARPS_N, int EPI, bool NT>
__global__ __launch_bounds__(256)
void gemm_tc(const float* __restrict__ A, const float* __restrict__ Bg,
             float* __restrict__ C, const float* __restrict__ bias,
             const float* __restrict__ res,
             int M, int N, int K, long sA, long sB, long sC, long sR,
             float scaleval)
{
    constexpr int BM = 128, BK = 16;
    constexpr int WM = BM / WARPS_M, WN = BN / WARPS_N;
    constexpr int MT = WM / 16, NTL = WN / 8;

    const int z = blockIdx.z;
    A  += (long)z * sA;
    Bg += (long)z * sB;
    C  += (long)z * sC;
    if (res) res += (long)z * sR;

    __shared__ float As[BK][BM + 4];   // [k][m]
    __shared__ float Bs[BK][BN + 4];   // [k][n]

    const int tid  = threadIdx.x;
    const int warp = tid >> 5, lane = tid & 31;
    const int g = lane >> 2, tig = lane & 3;
    const int wm = warp % WARPS_M, wn = warp / WARPS_M;
    const int m_base = wm * WM, n_base = wn * WN;
    const int m0 = blockIdx.y * BM, n0 = blockIdx.x * BN;

    float acc[MT][NTL][4] = {};

    float4 areg[2];
    float4 breg[2];

    auto loadA = [&](int k0) {
#pragma unroll
        for (int i = 0; i < 2; i++) {
            int id = tid * 2 + i;
            int row = id >> 2, c4 = (id & 3) * 4;
            areg[i] = *(const float4*)(A + (long)(m0 + row) * K + k0 + c4);
        }
    };
    auto storeA = [&]() {
#pragma unroll
        for (int i = 0; i < 2; i++) {
            int id = tid * 2 + i;
            int row = id >> 2, c4 = (id & 3) * 4;
            As[c4 + 0][row] = to_tf32(areg[i].x);
            As[c4 + 1][row] = to_tf32(areg[i].y);
            As[c4 + 2][row] = to_tf32(areg[i].z);
            As[c4 + 3][row] = to_tf32(areg[i].w);
        }
    };
    auto loadB = [&](int k0) {
        if constexpr (!NT) {
            if constexpr (BN == 128) {
#pragma unroll
                for (int i = 0; i < 2; i++) {
                    int id = tid * 2 + i;
                    int k = id >> 5, n4 = (id & 31) * 4;
                    breg[i] = *(const float4*)(Bg + (long)(k0 + k) * N + n0 + n4);
                }
            } else {  // BN == 64
                int k = tid >> 4, n4 = (tid & 15) * 4;
                breg[0] = *(const float4*)(Bg + (long)(k0 + k) * N + n0 + n4);
            }
        } else {      // NT, BN == 128: Bg is [N,K] row-major
#pragma unroll
            for (int i = 0; i < 2; i++) {
                int id = tid * 2 + i;
                int n = id >> 2, c4 = (id & 3) * 4;
                breg[i] = *(const float4*)(Bg + (long)(n0 + n) * K + k0 + c4);
            }
        }
    };
    auto storeB = [&]() {
        if constexpr (!NT) {
            if constexpr (BN == 128) {
#pragma unroll
                for (int i = 0; i < 2; i++) {
                    int id = tid * 2 + i;
                    int k = id >> 5, n4 = (id & 31) * 4;
                    float4 v = breg[i];
                    *(float4*)&Bs[k][n4] = make_float4(to_tf32(v.x), to_tf32(v.y),
                                                      to_tf32(v.z), to_tf32(v.w));
                }
            } else {
                int k = tid >> 4, n4 = (tid & 15) * 4;
                float4 v = breg[0];
                *(float4*)&Bs[k][n4] = make_float4(to_tf32(v.x), to_tf32(v.y),
                                                   to_tf32(v.z), to_tf32(v.w));
            }
        } else {
#pragma unroll
            for (int i = 0; i < 2; i++) {
                int id = tid * 2 + i;
                int n = id >> 2, c4 = (id & 3) * 4;
                float4 v = breg[i];
                Bs[c4 + 0][n] = to_tf32(v.x);
                Bs[c4 + 1][n] = to_tf32(v.y);
                Bs[c4 + 2][n] = to_tf32(v.z);
                Bs[c4 + 3][n] = to_tf32(v.w);
            }
        }
    };
    auto compute = [&]() {
#pragma unroll
        for (int ks = 0; ks < 2; ks++) {
            const int kk = ks * 8;
            uint32_t af[MT][4], bf[NTL][2];
#pragma unroll
            for (int mt = 0; mt < MT; mt++) {
                int r = m_base + mt * 16 + g;
                af[mt][0] = __float_as_uint(As[kk + tig][r]);
                af[mt][1] = __float_as_uint(As[kk + tig][r + 8]);
                af[mt][2] = __float_as_uint(As[kk + tig + 4][r]);
                af[mt][3] = __float_as_uint(As[kk + tig + 4][r + 8]);
            }
#pragma unroll
            for (int nt = 0; nt < NTL; nt++) {
                int cc = n_base + nt * 8 + g;
                bf[nt][0] = __float_as_uint(Bs[kk + tig][cc]);
                bf[nt][1] = __float_as_uint(Bs[kk + tig + 4][cc]);
            }
#pragma unroll
            for (int mt = 0; mt < MT; mt++)
#pragma unroll
                for (int nt = 0; nt < NTL; nt++)
                    mma_tf32(acc[mt][nt], af[mt], bf[nt]);
        }
    };

    // prologue: fill first tile
    loadA(0); loadB(0);
    storeA(); storeB();
    for (int k0 = BK; k0 < K; k0 += BK) {
        __syncthreads();
        loadA(k0); loadB(k0);     // prefetch next into regs
        compute();                // consume current smem tile
        __syncthreads();
        storeA(); storeB();
    }
    __syncthreads();
    compute();

    // epilogue
    auto emit = [&](int m, int n, float v) {
        if constexpr (EPI == 1) {
            v = (v + bias[n]) * scaleval;
            int b = m >> 9, s = m & 511, hh = n >> 6, d = n & 63;
            C[((((long)b * H_ + hh) * S_ + s) * DH_) + d] = v;
        } else if constexpr (EPI == 2) {
            C[(long)m * N + n] = v + bias[n] + res[(long)m * N + n];
        } else if constexpr (EPI == 3) {
            float x = v + bias[n];
            C[(long)m * N + n] = 0.5f * x * (1.0f + erff(x * 0.70710678118654752f));
        } else if constexpr (EPI == 4) {
            int b = z / H_, hh = z % H_;
            C[((long)(b * S_ + m)) * D_ + hh * DH_ + n] = v;
        } else if constexpr (EPI == 5) {
            long idx = (long)m * S_ + n;
            C[idx] = v + res[idx];
        }
    };
#pragma unroll
    for (int mt = 0; mt < MT; mt++) {
        int r0 = m0 + m_base + mt * 16 + g;
#pragma unroll
        for (int nt = 0; nt < NTL; nt++) {
            int c0 = n0 + n_base + nt * 8 + 2 * tig;
            emit(r0,     c0,     acc[mt][nt][0]);
            emit(r0,     c0 + 1, acc[mt][nt][1]);
            emit(r0 + 8, c0,     acc[mt][nt][2]);
            emit(r0 + 8, c0 + 1, acc[mt][nt][3]);
        }
    }
}

// ---------------- softmax over rows of length 512 ----------------
__global__ __launch_bounds__(256)
void softmax512(float* __restrict__ sc)
{
    float* row = sc + (long)blockIdx.x * S_;
    int tid = threadIdx.x;
    float v0 = row[tid], v1 = row[tid + 256];
    __shared__ float red[8];

    float m = fmaxf(v0, v1);
#pragma unroll
    for (int o = 16; o; o >>= 1) m = fmaxf(m, __shfl_xor_sync(0xffffffffu, m, o));
    if ((tid & 31) == 0) red[tid >> 5] = m;
    __syncthreads();
    m = fmaxf(fmaxf(fmaxf(red[0], red[1]), fmaxf(red[2], red[3])),
              fmaxf(fmaxf(red[4], red[5]), fmaxf(red[6], red[7])));
    __syncthreads();

    float e0 = __expf(v0 - m), e1 = __expf(v1 - m);
    float s = e0 + e1;
#pragma unroll
    for (int o = 16; o; o >>= 1) s += __shfl_xor_sync(0xffffffffu, s, o);
    if ((tid & 31) == 0) red[tid >> 5] = s;
    __syncthreads();
    s = (red[0] + red[1]) + (red[2] + red[3]) + (red[4] + red[5]) + (red[6] + red[7]);
    float inv = 1.0f / s;
    row[tid]       = e0 * inv;
    row[tid + 256] = e1 * inv;
}

// ---------------- layernorm over rows of length 768 ----------------
__global__ __launch_bounds__(256)
void layernorm768(const float* __restrict__ x, const float* __restrict__ g,
                  const float* __restrict__ b, float* __restrict__ y)
{
    const float* row = x + (long)blockIdx.x * D_;
    float* orow = y + (long)blockIdx.x * D_;
    int tid = threadIdx.x;
    float a0 = row[tid], a1 = row[tid + 256], a2 = row[tid + 512];
    float s = a0 + a1 + a2;
    float q = a0 * a0 + a1 * a1 + a2 * a2;
    __shared__ float rs[8], rq[8];
#pragma unroll
    for (int o = 16; o; o >>= 1) {
        s += __shfl_xor_sync(0xffffffffu, s, o);
        q += __shfl_xor_sync(0xffffffffu, q, o);
    }
    if ((tid & 31) == 0) { rs[tid >> 5] = s; rq[tid >> 5] = q; }
    __syncthreads();
    s = (rs[0] + rs[1]) + (rs[2] + rs[3]) + (rs[4] + rs[5]) + (rs[6] + rs[7]);
    q = (rq[0] + rq[1]) + (rq[2] + rq[3]) + (rq[4] + rq[5]) + (rq[6] + rq[7]);
    float mean = s * (1.0f / D_);
    float var  = q * (1.0f / D_) - mean * mean;
    float r = rsqrtf(var + 1e-5f);
    orow[tid]       = (a0 - mean) * r * g[tid]       + b[tid];
    orow[tid + 256] = (a1 - mean) * r * g[tid + 256] + b[tid + 256];
    orow[tid + 512] = (a2 - mean) * r * g[tid + 512] + b[tid + 512];
}

// ---------------- host orchestration ----------------
extern "C" void kernel_launch(void* const* d_in, const int* in_sizes, int n_in,
                              void* d_out, int out_size)
{
    const float* hs    = (const float*)d_in[0];
    const float* mask  = (const float*)d_in[1];
    const float* rel   = (const float*)d_in[2];
    const float* rel2  = (const float*)d_in[3];
    const float* Wq    = (const float*)d_in[4];
    const float* bq    = (const float*)d_in[5];
    const float* Wk    = (const float*)d_in[6];
    const float* bk    = (const float*)d_in[7];
    const float* Wv    = (const float*)d_in[8];
    const float* bv    = (const float*)d_in[9];
    const float* Wo    = (const float*)d_in[10];
    const float* bo    = (const float*)d_in[11];
    const float* ln1g  = (const float*)d_in[12];
    const float* ln1b  = (const float*)d_in[13];
    const float* Wi    = (const float*)d_in[14];
    const float* bi    = (const float*)d_in[15];
    const float* Wo2   = (const float*)d_in[16];
    const float* bo2   = (const float*)d_in[17];
    const float* ln2g  = (const float*)d_in[18];
    const float* ln2b  = (const float*)d_in[19];
    float* out = (float*)d_out;

    float *p_bias, *p_scores, *p_q, *p_k, *p_v, *p_ctx, *p_h, *p_tmp, *p_attn, *p_ff;
    cudaGetSymbolAddress((void**)&p_bias,   g_bias);
    cudaGetSymbolAddress((void**)&p_scores, g_scores);
    cudaGetSymbolAddress((void**)&p_q,      g_q);
    cudaGetSymbolAddress((void**)&p_k,      g_k);
    cudaGetSymbolAddress((void**)&p_v,      g_v);
    cudaGetSymbolAddress((void**)&p_ctx,    g_ctx);
    cudaGetSymbolAddress((void**)&p_h,      g_h);
    cudaGetSymbolAddress((void**)&p_tmp,    g_tmp);
    cudaGetSymbolAddress((void**)&p_attn,   g_attn);
    cudaGetSymbolAddress((void**)&p_ff,     g_ff);

    long nb = (long)BH_ * SS_;
    bias_kernel<<<(unsigned)((nb + 255) / 256), 256>>>(rel, rel2, mask);
    copy_kernel<<<(MR_ * D_ + 255) / 256, 256>>>(hs, p_h, (long)MR_ * D_);

    dim3 gQKV(D_ / 128, MR_ / 128, 1);      // 6 x 16
    dim3 gS  (S_ / 128, S_ / 128, BH_);     // 4 x 4 x 48
    dim3 gC  (1, S_ / 128, BH_);            // 1 x 4 x 48
    dim3 gF1 (FF_ / 128, MR_ / 128, 1);     // 24 x 16

    for (int l = 0; l < L_; l++) {
        const float* wq  = Wq  + (long)l * D_ * D_;
        const float* wk  = Wk  + (long)l * D_ * D_;
        const float* wv  = Wv  + (long)l * D_ * D_;
        const float* wo  = Wo  + (long)l * D_ * D_;
        const float* wi  = Wi  + (long)l * D_ * FF_;
        const float* wo2 = Wo2 + (long)l * FF_ * D_;

        // QKV projections (q folds 1/sqrt(DH)), scattered to [B,H,S,DH]
        gemm_tc<128,2,4,1,false><<<gQKV, 256>>>(p_h, wq, p_q, bq + l * D_, nullptr,
                                                MR_, D_, D_, 0, 0, 0, 0, 0.125f);
        gemm_tc<128,2,4,1,false><<<gQKV, 256>>>(p_h, wk, p_k, bk + l * D_, nullptr,
                                                MR_, D_, D_, 0, 0, 0, 0, 1.0f);
        gemm_tc<128,2,4,1,false><<<gQKV, 256>>>(p_h, wv, p_v, bv + l * D_, nullptr,
                                                MR_, D_, D_, 0, 0, 0, 0, 1.0f);

        // scores = q @ k^T + bias ; softmax (PB-Relax == standard safe softmax)
        gemm_tc<128,2,4,5,true><<<gS, 256>>>(p_q, p_k, p_scores, nullptr, p_bias,
                                             S_, S_, DH_,
                                             (long)S_ * DH_, (long)S_ * DH_,
                                             (long)SS_, (long)SS_, 1.0f);
        softmax512<<<BH_ * S_, 256>>>(p_scores);

        // ctx = probs @ v, gathered back to [B,S,D]
        gemm_tc<64,4,2,4,false><<<gC, 256>>>(p_scores, p_v, p_ctx, nullptr, nullptr,
                                             S_, DH_, S_,
                                             (long)SS_, (long)S_ * DH_, 0, 0, 1.0f);

        // attn_out = LN1(ctx @ Wo + bo + h)
        gemm_tc<128,2,4,2,false><<<gQKV, 256>>>(p_ctx, wo, p_tmp, bo + l * D_, p_h,
                                                MR_, D_, D_, 0, 0, 0, 0, 1.0f);
        layernorm768<<<MR_, 256>>>(p_tmp, ln1g + l * D_, ln1b + l * D_, p_attn);

        // ff = gelu(attn @ Wi + bi)
        gemm_tc<128,2,4,3,false><<<gF1, 256>>>(p_attn, wi, p_ff, bi + l * FF_, nullptr,
                                               MR_, FF_, D_, 0, 0, 0, 0, 1.0f);

        // out = LN2(ff @ Wo2 + bo2 + attn_out)
        gemm_tc<128,2,4,2,false><<<gQKV, 256>>>(p_ff, wo2, p_tmp, bo2 + l * D_, p_attn,
                                                MR_, D_, FF_, 0, 0, 0, 0, 1.0f);
        float* dst = (l == L_ - 1) ? out : p_h;
        layernorm768<<<MR_, 256>>>(p_tmp, ln2g + l * D_, ln2b + l * D_, dst);
    }
}

// round 5
// speedup vs baseline: 2.1075x; 1.5601x over previous
#include <cuda_runtime.h>
#include <math.h>
#include <stdint.h>

// ---------------- problem constants ----------------
#define L_   12
#define B_   4
#define S_   512
#define D_   768
#define H_   12
#define DH_  64
#define FF_  3072
#define BH_  (B_*H_)        // 48
#define MR_  (B_*S_)        // 2048 rows of hidden
#define SS_  (S_*S_)        // 262144

// ---------------- scratch (device globals; allocation-free) ----------------
__device__ float g_bias  [BH_*SS_];
__device__ float g_scores[BH_*SS_];
__device__ float g_q  [BH_*S_*DH_];
__device__ float g_k  [BH_*S_*DH_];
__device__ float g_v  [BH_*S_*DH_];
__device__ float g_ctx [MR_*D_];
__device__ float g_h   [MR_*D_];
__device__ float g_tmp [MR_*D_];
__device__ float g_attn[MR_*D_];
__device__ float g_ff  [MR_*FF_];

// ---------------- helpers ----------------
__device__ __forceinline__ float to_tf32(float x)
{
    float r;
    asm("cvt.rna.tf32.f32 %0, %1;" : "=f"(r) : "f"(x));
    return r;
}

__device__ __forceinline__ void mma_tf32(float* c, const uint32_t* a, const uint32_t* b)
{
    asm("mma.sync.aligned.m16n8k8.row.col.f32.tf32.tf32.f32 "
        "{%0,%1,%2,%3}, {%4,%5,%6,%7}, {%8,%9}, {%0,%1,%2,%3};"
        : "+f"(c[0]), "+f"(c[1]), "+f"(c[2]), "+f"(c[3])
        : "r"(a[0]), "r"(a[1]), "r"(a[2]), "r"(a[3]),
          "r"(b[0]), "r"(b[1]));
}

// ---------------- small kernels ----------------
__global__ void bias_kernel(const float* __restrict__ rel,
                            const float* __restrict__ rel2,
                            const float* __restrict__ mask)
{
    long i = (long)blockIdx.x * 256 + threadIdx.x;
    if (i >= (long)BH_ * SS_) return;
    int b = (int)(i / ((long)H_ * SS_));
    int kcol = (int)(i & (S_ - 1));
    g_bias[i] = (rel[i] + rel2[i]) * 0.125f + mask[b * S_ + kcol];
}

__global__ void copy_kernel(const float* __restrict__ src, float* __restrict__ dst, long n)
{
    long i = (long)blockIdx.x * 256 + threadIdx.x;
    if (i < n) dst[i] = src[i];
}

// ---------------- tensor-core TF32 GEMM (double-buffered) ----------------
// C = A[M,K] @ B (NN: B[K,N]; NT: B[N,K]) with fused epilogue.
// BM=128, BK=16, 256 threads / 8 warps, __launch_bounds__(256,2).
// Smem row stride = +8 pad -> stride 136 == 8 (mod 32): conflict-free frags.
// EPI: 1 = fused QKV scatter to [B,H,S,DH]; block picks {Wq,Wk,Wv} by n-block
//      2 = acc + bias[n] + res[m*N+n]
//      3 = gelu(acc + bias[n])   (exact erf)
//      4 = ctx gather: C[(b*S+m)*D + h*DH + n], z=b*H+h
//      5 = scores: C[m*S+n] = acc + res[m*S+n]   (C,res z-strided)
template<int BN, int WARPS_M, int WARPS_N, int EPI, bool NT>
__global__ __launch_bounds__(256, 2)
void gemm_tc(const float* __restrict__ A, const float* __restrict__ Bg,
             float* __restrict__ C, const float* __restrict__ bias,
             const float* __restrict__ res,
             const float* __restrict__ Bg2, const float* __restrict__ bias2,
             float* __restrict__ C2,
             const float* __restrict__ Bg3, const float* __restrict__ bias3,
             float* __restrict__ C3,
             int M, int N, int K, long sA, long sB, long sC, long sR,
             float scaleval)
{
    constexpr int BM = 128, BK = 16;
    constexpr int WM = BM / WARPS_M, WN = BN / WARPS_N;
    constexpr int MT = WM / 16, NTL = WN / 8;
    constexpr int PAD = 8;

    const int z = blockIdx.z;
    A  += (long)z * sA;
    C  += (long)z * sC;
    if (res) res += (long)z * sR;

    int n0;
    if constexpr (EPI == 1) {
        // fused QKV: gridDim.x = 3*(N/BN); select weight/bias/output
        const int nb = N / BN;
        const int which = blockIdx.x / nb;
        n0 = (blockIdx.x % nb) * BN;
        if (which == 1) { Bg = Bg2; bias = bias2; C = C2; scaleval = 1.0f; }
        else if (which == 2) { Bg = Bg3; bias = bias3; C = C3; scaleval = 1.0f; }
    } else {
        Bg += (long)z * sB;
        n0 = blockIdx.x * BN;
    }
    const int m0 = blockIdx.y * BM;

    __shared__ float As[2][BK][BM + PAD];
    __shared__ float Bs[2][BK][BN + PAD];

    const int tid  = threadIdx.x;
    const int warp = tid >> 5, lane = tid & 31;
    const int g = lane >> 2, tig = lane & 3;
    const int wm = warp % WARPS_M, wn = warp / WARPS_M;
    const int m_base = wm * WM, n_base = wn * WN;

    float acc[MT][NTL][4] = {};
    float4 areg[2];
    float4 breg[2];

    auto loadA = [&](int k0) {
#pragma unroll
        for (int i = 0; i < 2; i++) {
            int id = tid * 2 + i;
            int row = id >> 2, c4 = (id & 3) * 4;
            areg[i] = *(const float4*)(A + (long)(m0 + row) * K + k0 + c4);
        }
    };
    auto storeA = [&](int buf) {
#pragma unroll
        for (int i = 0; i < 2; i++) {
            int id = tid * 2 + i;
            int row = id >> 2, c4 = (id & 3) * 4;
            As[buf][c4 + 0][row] = to_tf32(areg[i].x);
            As[buf][c4 + 1][row] = to_tf32(areg[i].y);
            As[buf][c4 + 2][row] = to_tf32(areg[i].z);
            As[buf][c4 + 3][row] = to_tf32(areg[i].w);
        }
    };
    auto loadB = [&](int k0) {
        if constexpr (!NT) {
            if constexpr (BN == 128) {
#pragma unroll
                for (int i = 0; i < 2; i++) {
                    int id = tid * 2 + i;
                    int k = id >> 5, n4 = (id & 31) * 4;
                    breg[i] = *(const float4*)(Bg + (long)(k0 + k) * N + n0 + n4);
                }
            } else {  // BN == 64
                int k = tid >> 4, n4 = (tid & 15) * 4;
                breg[0] = *(const float4*)(Bg + (long)(k0 + k) * N + n0 + n4);
            }
        } else {      // NT, BN == 128: Bg is [N,K] row-major
#pragma unroll
            for (int i = 0; i < 2; i++) {
                int id = tid * 2 + i;
                int n = id >> 2, c4 = (id & 3) * 4;
                breg[i] = *(const float4*)(Bg + (long)(n0 + n) * K + k0 + c4);
            }
        }
    };
    auto storeB = [&](int buf) {
        if constexpr (!NT) {
            if constexpr (BN == 128) {
#pragma unroll
                for (int i = 0; i < 2; i++) {
                    int id = tid * 2 + i;
                    int k = id >> 5, n4 = (id & 31) * 4;
                    float4 v = breg[i];
                    *(float4*)&Bs[buf][k][n4] = make_float4(to_tf32(v.x), to_tf32(v.y),
                                                            to_tf32(v.z), to_tf32(v.w));
                }
            } else {
                int k = tid >> 4, n4 = (tid & 15) * 4;
                float4 v = breg[0];
                *(float4*)&Bs[buf][k][n4] = make_float4(to_tf32(v.x), to_tf32(v.y),
                                                        to_tf32(v.z), to_tf32(v.w));
            }
        } else {
#pragma unroll
            for (int i = 0; i < 2; i++) {
                int id = tid * 2 + i;
                int n = id >> 2, c4 = (id & 3) * 4;
                float4 v = breg[i];
                Bs[buf][c4 + 0][n] = to_tf32(v.x);
                Bs[buf][c4 + 1][n] = to_tf32(v.y);
                Bs[buf][c4 + 2][n] = to_tf32(v.z);
                Bs[buf][c4 + 3][n] = to_tf32(v.w);
            }
        }
    };
    auto compute = [&](int buf) {
#pragma unroll
        for (int ks = 0; ks < 2; ks++) {
            const int kk = ks * 8;
            uint32_t af[MT][4], bf[NTL][2];
#pragma unroll
            for (int mt = 0; mt < MT; mt++) {
                int r = m_base + mt * 16 + g;
                af[mt][0] = __float_as_uint(As[buf][kk + tig][r]);
                af[mt][1] = __float_as_uint(As[buf][kk + tig][r + 8]);
                af[mt][2] = __float_as_uint(As[buf][kk + tig + 4][r]);
                af[mt][3] = __float_as_uint(As[buf][kk + tig + 4][r + 8]);
            }
#pragma unroll
            for (int nt = 0; nt < NTL; nt++) {
                int cc = n_base + nt * 8 + g;
                bf[nt][0] = __float_as_uint(Bs[buf][kk + tig][cc]);
                bf[nt][1] = __float_as_uint(Bs[buf][kk + tig + 4][cc]);
            }
#pragma unroll
            for (int mt = 0; mt < MT; mt++)
#pragma unroll
                for (int nt = 0; nt < NTL; nt++)
                    mma_tf32(acc[mt][nt], af[mt], bf[nt]);
        }
    };

    // prologue
    loadA(0); loadB(0);
    storeA(0); storeB(0);
    __syncthreads();
    int buf = 0;
    for (int k0 = BK; k0 < K; k0 += BK) {
        loadA(k0); loadB(k0);        // prefetch next tile into regs (LDG in flight)
        compute(buf);                // mma on current smem buffer
        storeA(buf ^ 1); storeB(buf ^ 1);
        __syncthreads();
        buf ^= 1;
    }
    compute(buf);

    // epilogue
    auto emit = [&](int m, int n, float v) {
        if constexpr (EPI == 1) {
            v = (v + bias[n]) * scaleval;
            int b = m >> 9, s = m & 511, hh = n >> 6, d = n & 63;
            C[((((long)b * H_ + hh) * S_ + s) * DH_) + d] = v;
        } else if constexpr (EPI == 2) {
            C[(long)m * N + n] = v + bias[n] + res[(long)m * N + n];
        } else if constexpr (EPI == 3) {
            float x = v + bias[n];
            C[(long)m * N + n] = 0.5f * x * (1.0f + erff(x * 0.70710678118654752f));
        } else if constexpr (EPI == 4) {
            int b = z / H_, hh = z % H_;
            C[((long)(b * S_ + m)) * D_ + hh * DH_ + n] = v;
        } else if constexpr (EPI == 5) {
            long idx = (long)m * S_ + n;
            C[idx] = v + res[idx];
        }
    };
#pragma unroll
    for (int mt = 0; mt < MT; mt++) {
        int r0 = m0 + m_base + mt * 16 + g;
#pragma unroll
        for (int nt = 0; nt < NTL; nt++) {
            int c0 = n0 + n_base + nt * 8 + 2 * tig;
            emit(r0,     c0,     acc[mt][nt][0]);
            emit(r0,     c0 + 1, acc[mt][nt][1]);
            emit(r0 + 8, c0,     acc[mt][nt][2]);
            emit(r0 + 8, c0 + 1, acc[mt][nt][3]);
        }
    }
}

// ---------------- softmax over rows of length 512 ----------------
__global__ __launch_bounds__(256)
void softmax512(float* __restrict__ sc)
{
    float* row = sc + (long)blockIdx.x * S_;
    int tid = threadIdx.x;
    float v0 = row[tid], v1 = row[tid + 256];
    __shared__ float red[8];

    float m = fmaxf(v0, v1);
#pragma unroll
    for (int o = 16; o; o >>= 1) m = fmaxf(m, __shfl_xor_sync(0xffffffffu, m, o));
    if ((tid & 31) == 0) red[tid >> 5] = m;
    __syncthreads();
    m = fmaxf(fmaxf(fmaxf(red[0], red[1]), fmaxf(red[2], red[3])),
              fmaxf(fmaxf(red[4], red[5]), fmaxf(red[6], red[7])));
    __syncthreads();

    float e0 = __expf(v0 - m), e1 = __expf(v1 - m);
    float s = e0 + e1;
#pragma unroll
    for (int o = 16; o; o >>= 1) s += __shfl_xor_sync(0xffffffffu, s, o);
    if ((tid & 31) == 0) red[tid >> 5] = s;
    __syncthreads();
    s = (red[0] + red[1]) + (red[2] + red[3]) + (red[4] + red[5]) + (red[6] + red[7]);
    float inv = 1.0f / s;
    row[tid]       = e0 * inv;
    row[tid + 256] = e1 * inv;
}

// ---------------- layernorm over rows of length 768 ----------------
__global__ __launch_bounds__(256)
void layernorm768(const float* __restrict__ x, const float* __restrict__ g,
                  const float* __restrict__ b, float* __restrict__ y)
{
    const float* row = x + (long)blockIdx.x * D_;
    float* orow = y + (long)blockIdx.x * D_;
    int tid = threadIdx.x;
    float a0 = row[tid], a1 = row[tid + 256], a2 = row[tid + 512];
    float s = a0 + a1 + a2;
    float q = a0 * a0 + a1 * a1 + a2 * a2;
    __shared__ float rs[8], rq[8];
#pragma unroll
    for (int o = 16; o; o >>= 1) {
        s += __shfl_xor_sync(0xffffffffu, s, o);
        q += __shfl_xor_sync(0xffffffffu, q, o);
    }
    if ((tid & 31) == 0) { rs[tid >> 5] = s; rq[tid >> 5] = q; }
    __syncthreads();
    s = (rs[0] + rs[1]) + (rs[2] + rs[3]) + (rs[4] + rs[5]) + (rs[6] + rs[7]);
    q = (rq[0] + rq[1]) + (rq[2] + rq[3]) + (rq[4] + rq[5]) + (rq[6] + rq[7]);
    float mean = s * (1.0f / D_);
    float var  = q * (1.0f / D_) - mean * mean;
    float r = rsqrtf(var + 1e-5f);
    orow[tid]       = (a0 - mean) * r * g[tid]       + b[tid];
    orow[tid + 256] = (a1 - mean) * r * g[tid + 256] + b[tid + 256];
    orow[tid + 512] = (a2 - mean) * r * g[tid + 512] + b[tid + 512];
}

// ---------------- host orchestration ----------------
extern "C" void kernel_launch(void* const* d_in, const int* in_sizes, int n_in,
                              void* d_out, int out_size)
{
    const float* hs    = (const float*)d_in[0];
    const float* mask  = (const float*)d_in[1];
    const float* rel   = (const float*)d_in[2];
    const float* rel2  = (const float*)d_in[3];
    const float* Wq    = (const float*)d_in[4];
    const float* bq    = (const float*)d_in[5];
    const float* Wk    = (const float*)d_in[6];
    const float* bk    = (const float*)d_in[7];
    const float* Wv    = (const float*)d_in[8];
    const float* bv    = (const float*)d_in[9];
    const float* Wo    = (const float*)d_in[10];
    const float* bo    = (const float*)d_in[11];
    const float* ln1g  = (const float*)d_in[12];
    const float* ln1b  = (const float*)d_in[13];
    const float* Wi    = (const float*)d_in[14];
    const float* bi    = (const float*)d_in[15];
    const float* Wo2   = (const float*)d_in[16];
    const float* bo2   = (const float*)d_in[17];
    const float* ln2g  = (const float*)d_in[18];
    const float* ln2b  = (const float*)d_in[19];
    float* out = (float*)d_out;

    float *p_bias, *p_scores, *p_q, *p_k, *p_v, *p_ctx, *p_h, *p_tmp, *p_attn, *p_ff;
    cudaGetSymbolAddress((void**)&p_bias,   g_bias);
    cudaGetSymbolAddress((void**)&p_scores, g_scores);
    cudaGetSymbolAddress((void**)&p_q,      g_q);
    cudaGetSymbolAddress((void**)&p_k,      g_k);
    cudaGetSymbolAddress((void**)&p_v,      g_v);
    cudaGetSymbolAddress((void**)&p_ctx,    g_ctx);
    cudaGetSymbolAddress((void**)&p_h,      g_h);
    cudaGetSymbolAddress((void**)&p_tmp,    g_tmp);
    cudaGetSymbolAddress((void**)&p_attn,   g_attn);
    cudaGetSymbolAddress((void**)&p_ff,     g_ff);

    long nb = (long)BH_ * SS_;
    bias_kernel<<<(unsigned)((nb + 255) / 256), 256>>>(rel, rel2, mask);
    copy_kernel<<<(MR_ * D_ + 255) / 256, 256>>>(hs, p_h, (long)MR_ * D_);

    dim3 gQKV(3 * D_ / 128, MR_ / 128, 1);  // 18 x 16 = 288 (fused Q,K,V)
    dim3 gS  (S_ / 128, S_ / 128, BH_);     // 4 x 4 x 48 = 768
    dim3 gC  (1, S_ / 128, BH_);            // 192
    dim3 gWo (D_ / 64, MR_ / 128, 1);       // 12 x 16 = 192 (BN=64)
    dim3 gF1 (FF_ / 128, MR_ / 128, 1);     // 24 x 16 = 384
    dim3 gF2 (D_ / 64, MR_ / 128, 1);       // 12 x 16 = 192 (BN=64)

    for (int l = 0; l < L_; l++) {
        const float* wq  = Wq  + (long)l * D_ * D_;
        const float* wk  = Wk  + (long)l * D_ * D_;
        const float* wv  = Wv  + (long)l * D_ * D_;
        const float* wo  = Wo  + (long)l * D_ * D_;
        const float* wi  = Wi  + (long)l * D_ * FF_;
        const float* wo2 = Wo2 + (long)l * FF_ * D_;

        // fused QKV projections (q folds 1/sqrt(DH)), scattered to [B,H,S,DH]
        gemm_tc<128,2,4,1,false><<<gQKV, 256>>>(
            p_h, wq, p_q, bq + l * D_, nullptr,
            wk, bk + l * D_, p_k,
            wv, bv + l * D_, p_v,
            MR_, D_, D_, 0, 0, 0, 0, 0.125f);

        // scores = q @ k^T + bias ; softmax
        gemm_tc<128,2,4,5,true><<<gS, 256>>>(
            p_q, p_k, p_scores, nullptr, p_bias,
            nullptr, nullptr, nullptr, nullptr, nullptr, nullptr,
            S_, S_, DH_, (long)S_ * DH_, (long)S_ * DH_,
            (long)SS_, (long)SS_, 1.0f);
        softmax512<<<BH_ * S_, 256>>>(p_scores);

        // ctx = probs @ v, gathered back to [B,S,D]
        gemm_tc<64,4,2,4,false><<<gC, 256>>>(
            p_scores, p_v, p_ctx, nullptr, nullptr,
            nullptr, nullptr, nullptr, nullptr, nullptr, nullptr,
            S_, DH_, S_, (long)SS_, (long)S_ * DH_, 0, 0, 1.0f);

        // attn_out = LN1(ctx @ Wo + bo + h)
        gemm_tc<64,4,2,2,false><<<gWo, 256>>>(
            p_ctx, wo, p_tmp, bo + l * D_, p_h,
            nullptr, nullptr, nullptr, nullptr, nullptr, nullptr,
            MR_, D_, D_, 0, 0, 0, 0, 1.0f);
        layernorm768<<<MR_, 256>>>(p_tmp, ln1g + l * D_, ln1b + l * D_, p_attn);

        // ff = gelu(attn @ Wi + bi)
        gemm_tc<128,2,4,3,false><<<gF1, 256>>>(
            p_attn, wi, p_ff, bi + l * FF_, nullptr,
            nullptr, nullptr, nullptr, nullptr, nullptr, nullptr,
            MR_, FF_, D_, 0, 0, 0, 0, 1.0f);

        // out = LN2(ff @ Wo2 + bo2 + attn_out)
        gemm_tc<64,4,2,2,false><<<gF2, 256>>>(
            p_ff, wo2, p_tmp, bo2 + l * D_, p_attn,
            nullptr, nullptr, nullptr, nullptr, nullptr, nullptr,
            MR_, D_, FF_, 0, 0, 0, 0, 1.0f);
        float* dst = (l == L_ - 1) ? out : p_h;
        layernorm768<<<MR_, 256>>>(p_tmp, ln2g + l * D_, ln2b + l * D_, dst);
    }
}